// round 10
// baseline (speedup 1.0000x reference)
#include <cuda_runtime.h>
#include <mma.h>
#include <math.h>

using namespace nvcuda;

#define N_NODES 100000
#define E_MAX   1600000
#define HID     128
#define OUTD    64
#define PADN    100096   // N_NODES rounded up to multiple of 128
#define SCAN_BLK 1024
#define SCAN_NBLK ((N_NODES + SCAN_BLK - 1) / SCAN_BLK)   // 98

// ---------------- static scratch (no allocation allowed) ----------------
__device__ int    g_is64;
__device__ int    g_src[E_MAX];
__device__ int    g_dst[E_MAX];
__device__ int    g_col[E_MAX];
__device__ int    g_deg[N_NODES];
__device__ float  g_dinv[N_NODES];
__device__ int    g_rowptr[N_NODES + 1];
__device__ int    g_cursor[N_NODES];
__device__ int    g_part[SCAN_NBLK];
__device__ float4 g_h1 [PADN * (HID / 4)];   // x@W1 (unscaled)
__device__ float4 g_a1 [PADN * (HID / 4)];   // relu(layer1 out)
__device__ float4 g_h2 [PADN * (OUTD / 4)];  // a1@W2 (unscaled)

// ---------------- init + sampled dtype detection ----------------
__global__ void k_init() {
    int i = blockIdx.x * blockDim.x + threadIdx.x;
    if (i == 0) g_is64 = 1;
    if (i < N_NODES) g_deg[i] = 1;   // self loop
}

// Probe ~1024 spread slots of the int64 view. If data is int32, a slot fuses
// two random ints -> out of [0,N) with prob ~1-1e-5 per slot; 1024 probes
// make misdetection impossible in practice.
__global__ void k_detect(const long long* __restrict__ ei, int E) {
    int i = threadIdx.x;
    int stride = E / 1024; if (stride < 1) stride = 1;
    long long idx = (long long)i * stride;
    if (idx < E) {
        long long v = ei[idx];
        if (v < 0 || v >= (long long)N_NODES) g_is64 = 0;
    }
}

__global__ void k_edges(const void* __restrict__ eiv, int E) {
    int i = blockIdx.x * blockDim.x + threadIdx.x;
    if (i >= E) return;
    int s, d;
    if (g_is64) {
        const long long* p = (const long long*)eiv;
        s = (int)p[i];
        d = (int)p[E + i];
    } else {
        const int* p = (const int*)eiv;
        s = p[i];
        d = p[E + i];
    }
    if ((unsigned)s >= (unsigned)N_NODES) s = 0;   // defensive: never trap
    if ((unsigned)d >= (unsigned)N_NODES) d = 0;
    g_src[i] = s;
    g_dst[i] = d;
    atomicAdd(&g_deg[d], 1);
}

__global__ void k_dinv() {
    int i = blockIdx.x * blockDim.x + threadIdx.x;
    if (i < N_NODES) g_dinv[i] = rsqrtf((float)g_deg[i]);
}

// ---------------- parallel exclusive scan of (deg-1) ----------------
__global__ void k_scan1() {
    __shared__ int sh[SCAN_BLK];
    int i = blockIdx.x * SCAN_BLK + threadIdx.x;
    int v = (i < N_NODES) ? g_deg[i] - 1 : 0;
    sh[threadIdx.x] = v;
    __syncthreads();
    for (int off = SCAN_BLK / 2; off; off >>= 1) {
        if (threadIdx.x < off) sh[threadIdx.x] += sh[threadIdx.x + off];
        __syncthreads();
    }
    if (threadIdx.x == 0) g_part[blockIdx.x] = sh[0];
}

__global__ void k_scan2() {
    __shared__ int sh[128];
    int t = threadIdx.x;
    int v = (t < SCAN_NBLK) ? g_part[t] : 0;
    sh[t] = v;
    __syncthreads();
    for (int off = 1; off < 128; off <<= 1) {
        int a = (t >= off) ? sh[t - off] : 0;
        __syncthreads();
        sh[t] += a;
        __syncthreads();
    }
    if (t < SCAN_NBLK) g_part[t] = sh[t] - v;   // exclusive
}

__global__ void k_scan3(int E) {
    __shared__ int sh[SCAN_BLK];
    int i = blockIdx.x * SCAN_BLK + threadIdx.x;
    int v = (i < N_NODES) ? g_deg[i] - 1 : 0;
    sh[threadIdx.x] = v;
    __syncthreads();
    for (int off = 1; off < SCAN_BLK; off <<= 1) {
        int a = (threadIdx.x >= off) ? sh[threadIdx.x - off] : 0;
        __syncthreads();
        sh[threadIdx.x] += a;
        __syncthreads();
    }
    int excl = sh[threadIdx.x] - v + g_part[blockIdx.x];
    if (i < N_NODES) {
        g_rowptr[i] = excl;
        g_cursor[i] = excl;
    }
    if (i == 0) g_rowptr[N_NODES] = E;
}

__global__ void k_scatter(int E) {
    int i = blockIdx.x * blockDim.x + threadIdx.x;
    if (i < E) {
        int d = g_dst[i];
        int p = atomicAdd(&g_cursor[d], 1);
        g_col[p] = g_src[i];
    }
}

// ---------------- split-TF32 helpers ----------------
template <typename FragIn, typename Frag>
__device__ __forceinline__ void split_tf32(const FragIn& raw, Frag& hi, Frag& lo) {
#pragma unroll
    for (int i = 0; i < raw.num_elements; i++) {
        float v = raw.x[i];
        float h = wmma::__float_to_tf32(v);
        hi.x[i] = h;
        lo.x[i] = wmma::__float_to_tf32(v - h);
    }
}

// ---------------- GEMM 1: h1 = X @ W1   [100000x128 @ 128x128]
// Split-TF32 wmma. 256 threads = 8 warps; block tile 128x128; warp w does
// rows w*16..w*16+15, all 128 cols (8 n-tiles). K chunk = 16.
__global__ void k_gemm1(const float* __restrict__ X, const float* __restrict__ W) {
    __shared__ float As[128][20];    // [m][k] row-major, ldm 20 (mult of 4)
    __shared__ float Bs[16][128];    // [k][n] row-major, ldm 128
    int tid = threadIdx.x;
    int w   = tid >> 5;
    int row0 = blockIdx.x * 128;
    float* h1f = (float*)g_h1;

    wmma::fragment<wmma::accumulator, 16, 16, 8, float> c[8];
#pragma unroll
    for (int n = 0; n < 8; n++) wmma::fill_fragment(c[n], 0.f);

    int am = tid >> 1;            // A-load row 0..127
    int ak = (tid & 1) * 8;       // A-load k offset 0/8
    int bk = tid >> 4;            // B-load k row 0..15
    int bc = (tid & 15) * 8;      // B-load col

    for (int k0 = 0; k0 < HID; k0 += 16) {
        int row = row0 + am;
        float4 v0, v1;
        if (row < N_NODES) {
            v0 = *(const float4*)(X + row * HID + k0 + ak);
            v1 = *(const float4*)(X + row * HID + k0 + ak + 4);
        } else {
            v0 = make_float4(0.f, 0.f, 0.f, 0.f);
            v1 = v0;
        }
        *(float4*)&As[am][ak]     = v0;
        *(float4*)&As[am][ak + 4] = v1;
        *(float4*)&Bs[bk][bc]     = *(const float4*)(W + (k0 + bk) * 128 + bc);
        *(float4*)&Bs[bk][bc + 4] = *(const float4*)(W + (k0 + bk) * 128 + bc + 4);
        __syncthreads();
#pragma unroll
        for (int kk = 0; kk < 16; kk += 8) {
            wmma::fragment<wmma::matrix_a, 16, 16, 8, wmma::precision::tf32, wmma::row_major> araw, ahi, alo;
            wmma::load_matrix_sync(araw, &As[w * 16][kk], 20);
            split_tf32(araw, ahi, alo);
#pragma unroll
            for (int n = 0; n < 8; n++) {
                wmma::fragment<wmma::matrix_b, 16, 16, 8, wmma::precision::tf32, wmma::row_major> braw, bhi, blo;
                wmma::load_matrix_sync(braw, &Bs[kk][n * 16], 128);
                split_tf32(braw, bhi, blo);
                wmma::mma_sync(c[n], ahi, bhi, c[n]);
                wmma::mma_sync(c[n], ahi, blo, c[n]);
                wmma::mma_sync(c[n], alo, bhi, c[n]);
            }
        }
        __syncthreads();
    }
#pragma unroll
    for (int n = 0; n < 8; n++)
        wmma::store_matrix_sync(h1f + (size_t)(row0 + w * 16) * HID + n * 16,
                                c[n], HID, wmma::mem_row_major);
}

// ---------------- aggregation layer 1 ----------------
// a1 = relu(dinv[v]*(dinv[v]*h1[v] + sum_in dinv[s]*h1[s]) + b1).
// Warp per node; lane owns float4 column group lane. 4-way edge unroll.
__global__ void k_agg1(const float* __restrict__ b1) {
    int gw   = (blockIdx.x * blockDim.x + threadIdx.x) >> 5;
    int lane = threadIdx.x & 31;
    if (gw >= N_NODES) return;
    const float4* __restrict__ hs = g_h1;
    const int* __restrict__ col = g_col;
    const float* __restrict__ dinv = g_dinv;
    float dvv = dinv[gw];
    float4 sv = hs[gw * 32 + lane];
    float4 acc  = make_float4(sv.x * dvv, sv.y * dvv, sv.z * dvv, sv.w * dvv);
    float4 acc2 = make_float4(0.f, 0.f, 0.f, 0.f);
    int beg = g_rowptr[gw], end = g_rowptr[gw + 1];
    int e = beg;
    for (; e + 3 < end; e += 4) {
        int s0 = col[e];
        int s1 = col[e + 1];
        int s2 = col[e + 2];
        int s3 = col[e + 3];
        float d0 = dinv[s0], d1 = dinv[s1], d2 = dinv[s2], d3 = dinv[s3];
        float4 v0 = hs[s0 * 32 + lane];
        float4 v1 = hs[s1 * 32 + lane];
        float4 v2 = hs[s2 * 32 + lane];
        float4 v3 = hs[s3 * 32 + lane];
        acc.x  = fmaf(v0.x, d0, acc.x);  acc.y  = fmaf(v0.y, d0, acc.y);
        acc.z  = fmaf(v0.z, d0, acc.z);  acc.w  = fmaf(v0.w, d0, acc.w);
        acc2.x = fmaf(v1.x, d1, acc2.x); acc2.y = fmaf(v1.y, d1, acc2.y);
        acc2.z = fmaf(v1.z, d1, acc2.z); acc2.w = fmaf(v1.w, d1, acc2.w);
        acc.x  = fmaf(v2.x, d2, acc.x);  acc.y  = fmaf(v2.y, d2, acc.y);
        acc.z  = fmaf(v2.z, d2, acc.z);  acc.w  = fmaf(v2.w, d2, acc.w);
        acc2.x = fmaf(v3.x, d3, acc2.x); acc2.y = fmaf(v3.y, d3, acc2.y);
        acc2.z = fmaf(v3.z, d3, acc2.z); acc2.w = fmaf(v3.w, d3, acc2.w);
    }
    for (; e < end; e++) {
        int s0 = col[e];
        float d0 = dinv[s0];
        float4 v0 = hs[s0 * 32 + lane];
        acc.x = fmaf(v0.x, d0, acc.x); acc.y = fmaf(v0.y, d0, acc.y);
        acc.z = fmaf(v0.z, d0, acc.z); acc.w = fmaf(v0.w, d0, acc.w);
    }
    acc.x += acc2.x; acc.y += acc2.y; acc.z += acc2.z; acc.w += acc2.w;
    float4 o;
    o.x = fmaxf(acc.x * dvv + b1[lane * 4 + 0], 0.f);
    o.y = fmaxf(acc.y * dvv + b1[lane * 4 + 1], 0.f);
    o.z = fmaxf(acc.z * dvv + b1[lane * 4 + 2], 0.f);
    o.w = fmaxf(acc.w * dvv + b1[lane * 4 + 3], 0.f);
    g_a1[gw * 32 + lane] = o;
}

// ---------------- GEMM 2: h2 = a1 @ W2   [100000x128 @ 128x64]
// Split-TF32 wmma. 256 threads; block tile 128x64; warp w: rows w*16..+15,
// 4 n-tiles of 16.
__global__ void k_gemm2(const float* __restrict__ W) {
    __shared__ float As[128][20];
    __shared__ float Bs[16][64];
    int tid = threadIdx.x;
    int w   = tid >> 5;
    int row0 = blockIdx.x * 128;
    const float* a1f = (const float*)g_a1;
    float* h2f = (float*)g_h2;

    wmma::fragment<wmma::accumulator, 16, 16, 8, float> c[4];
#pragma unroll
    for (int n = 0; n < 4; n++) wmma::fill_fragment(c[n], 0.f);

    int am = tid >> 1;
    int ak = (tid & 1) * 8;
    int bk = tid >> 4;            // 0..15
    int bc = (tid & 15) * 4;      // col

    for (int k0 = 0; k0 < HID; k0 += 16) {
        int row = row0 + am;
        // rows >= N_NODES read pad region of g_a1 (garbage ok: outputs for
        // those rows land in the pad region of g_h2 and are never consumed)
        float4 v0 = *(const float4*)(a1f + (size_t)row * HID + k0 + ak);
        float4 v1 = *(const float4*)(a1f + (size_t)row * HID + k0 + ak + 4);
        *(float4*)&As[am][ak]     = v0;
        *(float4*)&As[am][ak + 4] = v1;
        *(float4*)&Bs[bk][bc]     = *(const float4*)(W + (k0 + bk) * 64 + bc);
        __syncthreads();
#pragma unroll
        for (int kk = 0; kk < 16; kk += 8) {
            wmma::fragment<wmma::matrix_a, 16, 16, 8, wmma::precision::tf32, wmma::row_major> araw, ahi, alo;
            wmma::load_matrix_sync(araw, &As[w * 16][kk], 20);
            split_tf32(araw, ahi, alo);
#pragma unroll
            for (int n = 0; n < 4; n++) {
                wmma::fragment<wmma::matrix_b, 16, 16, 8, wmma::precision::tf32, wmma::row_major> braw, bhi, blo;
                wmma::load_matrix_sync(braw, &Bs[kk][n * 16], 64);
                split_tf32(braw, bhi, blo);
                wmma::mma_sync(c[n], ahi, bhi, c[n]);
                wmma::mma_sync(c[n], ahi, blo, c[n]);
                wmma::mma_sync(c[n], alo, bhi, c[n]);
            }
        }
        __syncthreads();
    }
#pragma unroll
    for (int n = 0; n < 4; n++)
        wmma::store_matrix_sync(h2f + (size_t)(row0 + w * 16) * OUTD + n * 16,
                                c[n], OUTD, wmma::mem_row_major);
}

// ---------------- aggregation layer 2 + bias + log_softmax ----------------
// Warp per node; lanes 0..15 own float4 group; lanes 16..31 join shuffles.
__global__ void k_agg2(const float* __restrict__ b2, float* __restrict__ out) {
    int gw   = (blockIdx.x * blockDim.x + threadIdx.x) >> 5;
    int lane = threadIdx.x & 31;
    if (gw >= N_NODES) return;
    const float4* __restrict__ hs = g_h2;
    const int* __restrict__ col = g_col;
    const float* __restrict__ dinv = g_dinv;
    bool active = lane < 16;
    int li = active ? lane : 0;
    float dvv = dinv[gw];
    float4 sv = hs[gw * 16 + li];
    float4 acc  = make_float4(sv.x * dvv, sv.y * dvv, sv.z * dvv, sv.w * dvv);
    float4 acc2 = make_float4(0.f, 0.f, 0.f, 0.f);
    int beg = g_rowptr[gw], end = g_rowptr[gw + 1];
    int e = beg;
    for (; e + 3 < end; e += 4) {
        int s0 = col[e];
        int s1 = col[e + 1];
        int s2 = col[e + 2];
        int s3 = col[e + 3];
        float d0 = dinv[s0], d1 = dinv[s1], d2 = dinv[s2], d3 = dinv[s3];
        float4 v0 = hs[s0 * 16 + li];
        float4 v1 = hs[s1 * 16 + li];
        float4 v2 = hs[s2 * 16 + li];
        float4 v3 = hs[s3 * 16 + li];
        acc.x  = fmaf(v0.x, d0, acc.x);  acc.y  = fmaf(v0.y, d0, acc.y);
        acc.z  = fmaf(v0.z, d0, acc.z);  acc.w  = fmaf(v0.w, d0, acc.w);
        acc2.x = fmaf(v1.x, d1, acc2.x); acc2.y = fmaf(v1.y, d1, acc2.y);
        acc2.z = fmaf(v1.z, d1, acc2.z); acc2.w = fmaf(v1.w, d1, acc2.w);
        acc.x  = fmaf(v2.x, d2, acc.x);  acc.y  = fmaf(v2.y, d2, acc.y);
        acc.z  = fmaf(v2.z, d2, acc.z);  acc.w  = fmaf(v2.w, d2, acc.w);
        acc2.x = fmaf(v3.x, d3, acc2.x); acc2.y = fmaf(v3.y, d3, acc2.y);
        acc2.z = fmaf(v3.z, d3, acc2.z); acc2.w = fmaf(v3.w, d3, acc2.w);
    }
    for (; e < end; e++) {
        int s0 = col[e];
        float d0 = dinv[s0];
        float4 v0 = hs[s0 * 16 + li];
        acc.x = fmaf(v0.x, d0, acc.x); acc.y = fmaf(v0.y, d0, acc.y);
        acc.z = fmaf(v0.z, d0, acc.z); acc.w = fmaf(v0.w, d0, acc.w);
    }
    acc.x += acc2.x; acc.y += acc2.y; acc.z += acc2.z; acc.w += acc2.w;
    float o0 = acc.x * dvv + b2[li * 4 + 0];
    float o1 = acc.y * dvv + b2[li * 4 + 1];
    float o2 = acc.z * dvv + b2[li * 4 + 2];
    float o3 = acc.w * dvv + b2[li * 4 + 3];
    // log_softmax over 64 values (4 per active lane)
    float m = fmaxf(fmaxf(o0, o1), fmaxf(o2, o3));
    if (!active) m = -1e30f;
#pragma unroll
    for (int off = 16; off; off >>= 1)
        m = fmaxf(m, __shfl_xor_sync(0xffffffffu, m, off));
    float s2 = active ? (expf(o0 - m) + expf(o1 - m) + expf(o2 - m) + expf(o3 - m)) : 0.f;
#pragma unroll
    for (int off = 16; off; off >>= 1)
        s2 += __shfl_xor_sync(0xffffffffu, s2, off);
    float lse = m + logf(s2);
    if (active) {
        out[gw * OUTD + lane * 4 + 0] = o0 - lse;
        out[gw * OUTD + lane * 4 + 1] = o1 - lse;
        out[gw * OUTD + lane * 4 + 2] = o2 - lse;
        out[gw * OUTD + lane * 4 + 3] = o3 - lse;
    }
}

// ---------------- launch ----------------
extern "C" void kernel_launch(void* const* d_in, const int* in_sizes, int n_in,
                              void* d_out, int out_size) {
    const float* x  = (const float*)d_in[0];
    const void*  ei = d_in[1];
    const float* W1 = (const float*)d_in[2];
    const float* b1 = (const float*)d_in[3];
    const float* W2 = (const float*)d_in[4];
    const float* b2 = (const float*)d_in[5];
    float* out = (float*)d_out;

    int E = in_sizes[1] / 2;
    if (E > E_MAX) E = E_MAX;

    int nblkN = (N_NODES + 255) / 256;
    int nblkE = (E + 255) / 256;
    int nblkM = PADN / 128;                     // GEMM row blocks (782)
    int nblkW = (N_NODES * 32 + 255) / 256;     // warp-per-node kernels

    k_init<<<nblkN, 256>>>();
    k_detect<<<1, 1024>>>((const long long*)ei, E);
    k_edges<<<nblkE, 256>>>(ei, E);
    k_dinv<<<nblkN, 256>>>();
    k_scan1<<<SCAN_NBLK, SCAN_BLK>>>();
    k_scan2<<<1, 128>>>();
    k_scan3<<<SCAN_NBLK, SCAN_BLK>>>(E);
    k_scatter<<<nblkE, 256>>>(E);
    k_gemm1<<<nblkM, 256>>>(x, W1);
    k_agg1<<<nblkW, 256>>>(b1);
    k_gemm2<<<nblkM, 256>>>(W2);
    k_agg2<<<nblkW, 256>>>(b2, out);
}

// round 13
// speedup vs baseline: 1.3449x; 1.3449x over previous
#include <cuda_runtime.h>
#include <math.h>

#define N_NODES 100000
#define E_MAX   1600000
#define HID     128
#define OUTD    64
#define SCAN_BLK 1024
#define SCAN_NBLK ((N_NODES + SCAN_BLK - 1) / SCAN_BLK)   // 98

// ---------------- static scratch (no allocation allowed) ----------------
__device__ int    g_is64;
__device__ int    g_src[E_MAX];
__device__ int    g_dst[E_MAX];
__device__ int    g_col[E_MAX];
__device__ int    g_deg[N_NODES];
__device__ float  g_dinv[N_NODES];
__device__ int    g_rowptr[N_NODES + 1];
__device__ int    g_cursor[N_NODES];
__device__ int    g_part[SCAN_NBLK];
__device__ float4 g_hs1[N_NODES * (HID / 4)];   // (x@W1) * dinv[row]
__device__ float4 g_a1 [N_NODES * (HID / 4)];   // relu(layer1 out)
__device__ float4 g_hs2[N_NODES * (OUTD / 4)];  // (a1@W2) * dinv[row]

// ---------------- init + sampled dtype detection ----------------
__global__ void k_init() {
    int i = blockIdx.x * blockDim.x + threadIdx.x;
    if (i == 0) g_is64 = 1;
    if (i < N_NODES) g_deg[i] = 1;   // self loop
}

// Probe ~1024 spread slots of the int64 view. If data is int32, a slot fuses
// two random node ids -> out of [0,N) with prob ~1-1e-5 per slot; 1024 probes
// make misdetection vanishingly unlikely.
__global__ void k_detect(const long long* __restrict__ ei, int E) {
    int i = threadIdx.x;
    int stride = E / 1024; if (stride < 1) stride = 1;
    long long idx = (long long)i * stride;
    if (idx < E) {
        long long v = ei[idx];
        if (v < 0 || v >= (long long)N_NODES) g_is64 = 0;
    }
}

__global__ void k_edges(const void* __restrict__ eiv, int E) {
    int i = blockIdx.x * blockDim.x + threadIdx.x;
    if (i >= E) return;
    int s, d;
    if (g_is64) {
        const long long* p = (const long long*)eiv;
        s = (int)p[i];
        d = (int)p[E + i];
    } else {
        const int* p = (const int*)eiv;
        s = p[i];
        d = p[E + i];
    }
    if ((unsigned)s >= (unsigned)N_NODES) s = 0;   // defensive: never trap
    if ((unsigned)d >= (unsigned)N_NODES) d = 0;
    g_src[i] = s;
    g_dst[i] = d;
    atomicAdd(&g_deg[d], 1);
}

// ---------------- parallel exclusive scan of (deg-1); also computes dinv ----
__global__ void k_scan1() {
    __shared__ int sh[SCAN_BLK];
    int i = blockIdx.x * SCAN_BLK + threadIdx.x;
    int dg = (i < N_NODES) ? g_deg[i] : 1;
    if (i < N_NODES) g_dinv[i] = rsqrtf((float)dg);   // fused dinv
    int v = dg - 1;
    if (i >= N_NODES) v = 0;
    sh[threadIdx.x] = v;
    __syncthreads();
    for (int off = SCAN_BLK / 2; off; off >>= 1) {
        if (threadIdx.x < off) sh[threadIdx.x] += sh[threadIdx.x + off];
        __syncthreads();
    }
    if (threadIdx.x == 0) g_part[blockIdx.x] = sh[0];
}

__global__ void k_scan2() {
    __shared__ int sh[128];
    int t = threadIdx.x;
    int v = (t < SCAN_NBLK) ? g_part[t] : 0;
    sh[t] = v;
    __syncthreads();
    for (int off = 1; off < 128; off <<= 1) {
        int a = (t >= off) ? sh[t - off] : 0;
        __syncthreads();
        sh[t] += a;
        __syncthreads();
    }
    if (t < SCAN_NBLK) g_part[t] = sh[t] - v;   // exclusive
}

__global__ void k_scan3(int E) {
    __shared__ int sh[SCAN_BLK];
    int i = blockIdx.x * SCAN_BLK + threadIdx.x;
    int v = (i < N_NODES) ? g_deg[i] - 1 : 0;
    sh[threadIdx.x] = v;
    __syncthreads();
    for (int off = 1; off < SCAN_BLK; off <<= 1) {
        int a = (threadIdx.x >= off) ? sh[threadIdx.x - off] : 0;
        __syncthreads();
        sh[threadIdx.x] += a;
        __syncthreads();
    }
    int excl = sh[threadIdx.x] - v + g_part[blockIdx.x];
    if (i < N_NODES) {
        g_rowptr[i] = excl;
        g_cursor[i] = excl;
    }
    if (i == 0) g_rowptr[N_NODES] = E;
}

__global__ void k_scatter(int E) {
    int i = blockIdx.x * blockDim.x + threadIdx.x;
    if (i < E) {
        int d = g_dst[i];
        int p = atomicAdd(&g_cursor[d], 1);
        g_col[p] = g_src[i];
    }
}

// ---------------- GEMM 1: hs1 = (X @ W1) * dinv[row]   [100000x128 @ 128x128]
// BM=128 BN=128 BK=8, 256 threads, 8x8 micro-tile, float4 LDS.
__global__ void k_gemm1(const float* __restrict__ X, const float* __restrict__ W) {
    __shared__ float As[8][128];
    __shared__ float Bs[8][128];
    int tid = threadIdx.x;
    int tr = tid >> 4;          // 0..15 -> rows tr*8..tr*8+7
    int tc = tid & 15;          // 0..15 -> cols tc*8..tc*8+7
    int row0 = blockIdx.x * 128;
    int lm = tid >> 1;          // A-load: row within tile (0..127)
    int lk = (tid & 1) * 4;     // A-load: k offset 0 or 4
    int bk = tid >> 5;          // B-load: k row (0..7)
    int bc = (tid & 31) * 4;    // B-load: col*4
    float acc[8][8];
#pragma unroll
    for (int r = 0; r < 8; r++)
#pragma unroll
        for (int c = 0; c < 8; c++) acc[r][c] = 0.f;

    for (int k0 = 0; k0 < HID; k0 += 8) {
        int row = row0 + lm;
        float4 av = (row < N_NODES) ? *(const float4*)(X + row * HID + k0 + lk)
                                    : make_float4(0.f, 0.f, 0.f, 0.f);
        As[lk + 0][lm] = av.x;
        As[lk + 1][lm] = av.y;
        As[lk + 2][lm] = av.z;
        As[lk + 3][lm] = av.w;
        *(float4*)&Bs[bk][bc] = *(const float4*)(W + (k0 + bk) * 128 + bc);
        __syncthreads();
        float ar[8], br[8];
#pragma unroll
        for (int k = 0; k < 8; k++) {
            *(float4*)&ar[0] = *(float4*)&As[k][tr * 8];
            *(float4*)&ar[4] = *(float4*)&As[k][tr * 8 + 4];
            *(float4*)&br[0] = *(float4*)&Bs[k][tc * 8];
            *(float4*)&br[4] = *(float4*)&Bs[k][tc * 8 + 4];
#pragma unroll
            for (int r = 0; r < 8; r++)
#pragma unroll
                for (int c = 0; c < 8; c++)
                    acc[r][c] += ar[r] * br[c];
        }
        __syncthreads();
    }
#pragma unroll
    for (int r = 0; r < 8; r++) {
        int row = row0 + tr * 8 + r;
        if (row < N_NODES) {
            float dv = g_dinv[row];
            float4 o0 = make_float4(acc[r][0] * dv, acc[r][1] * dv,
                                    acc[r][2] * dv, acc[r][3] * dv);
            float4 o1 = make_float4(acc[r][4] * dv, acc[r][5] * dv,
                                    acc[r][6] * dv, acc[r][7] * dv);
            g_hs1[row * 32 + tc * 2 + 0] = o0;
            g_hs1[row * 32 + tc * 2 + 1] = o1;
        }
    }
}

// ---------------- aggregation layer 1 ----------------
// a1 = relu(dinv[v]*(hs1[v] + sum_in hs1[s]) + b1). Warp per node;
// lane owns float4 column group lane. 4-way edge unroll for gather MLP.
__global__ void k_agg1(const float* __restrict__ b1) {
    int gw   = (blockIdx.x * blockDim.x + threadIdx.x) >> 5;
    int lane = threadIdx.x & 31;
    if (gw >= N_NODES) return;
    const float4* __restrict__ hs = g_hs1;
    const int* __restrict__ col = g_col;
    float4 acc = hs[gw * 32 + lane];   // self loop (pre-scaled)
    float4 acc2 = make_float4(0.f, 0.f, 0.f, 0.f);
    int beg = g_rowptr[gw], end = g_rowptr[gw + 1];
    int e = beg;
    for (; e + 3 < end; e += 4) {
        int s0 = col[e];
        int s1 = col[e + 1];
        int s2 = col[e + 2];
        int s3 = col[e + 3];
        float4 v0 = hs[s0 * 32 + lane];
        float4 v1 = hs[s1 * 32 + lane];
        float4 v2 = hs[s2 * 32 + lane];
        float4 v3 = hs[s3 * 32 + lane];
        acc.x  += v0.x; acc.y  += v0.y; acc.z  += v0.z; acc.w  += v0.w;
        acc2.x += v1.x; acc2.y += v1.y; acc2.z += v1.z; acc2.w += v1.w;
        acc.x  += v2.x; acc.y  += v2.y; acc.z  += v2.z; acc.w  += v2.w;
        acc2.x += v3.x; acc2.y += v3.y; acc2.z += v3.z; acc2.w += v3.w;
    }
    for (; e < end; e++) {
        int s0 = col[e];
        float4 v0 = hs[s0 * 32 + lane];
        acc.x += v0.x; acc.y += v0.y; acc.z += v0.z; acc.w += v0.w;
    }
    acc.x += acc2.x; acc.y += acc2.y; acc.z += acc2.z; acc.w += acc2.w;
    float dv = g_dinv[gw];
    float4 o;
    o.x = fmaxf(acc.x * dv + b1[lane * 4 + 0], 0.f);
    o.y = fmaxf(acc.y * dv + b1[lane * 4 + 1], 0.f);
    o.z = fmaxf(acc.z * dv + b1[lane * 4 + 2], 0.f);
    o.w = fmaxf(acc.w * dv + b1[lane * 4 + 3], 0.f);
    g_a1[gw * 32 + lane] = o;
}

// ---------------- GEMM 2: hs2 = (a1 @ W2) * dinv[row]   [100000x128 @ 128x64]
// BM=128 BN=64 BK=8, 256 threads, 8x4 micro-tile.
__global__ void k_gemm2(const float* __restrict__ W) {
    __shared__ float As[8][128];
    __shared__ float Bs[8][64];
    int tid = threadIdx.x;
    int tr = tid >> 4;          // 0..15 -> rows tr*8..tr*8+7
    int tc = tid & 15;          // 0..15 -> cols tc*4..tc*4+3
    int row0 = blockIdx.x * 128;
    int lm = tid >> 1;
    int lk = (tid & 1) * 4;
    int bk = tid >> 5;          // 0..7
    int bc = (tid & 31) * 2;    // col*2
    const float* __restrict__ a1f = (const float*)g_a1;
    float acc[8][4];
#pragma unroll
    for (int r = 0; r < 8; r++)
#pragma unroll
        for (int c = 0; c < 4; c++) acc[r][c] = 0.f;

    for (int k0 = 0; k0 < HID; k0 += 8) {
        int row = row0 + lm;
        float4 av = (row < N_NODES) ? *(const float4*)(a1f + row * HID + k0 + lk)
                                    : make_float4(0.f, 0.f, 0.f, 0.f);
        As[lk + 0][lm] = av.x;
        As[lk + 1][lm] = av.y;
        As[lk + 2][lm] = av.z;
        As[lk + 3][lm] = av.w;
        *(float2*)&Bs[bk][bc] = *(const float2*)(W + (k0 + bk) * 64 + bc);
        __syncthreads();
        float ar[8], br[4];
#pragma unroll
        for (int k = 0; k < 8; k++) {
            *(float4*)&ar[0] = *(float4*)&As[k][tr * 8];
            *(float4*)&ar[4] = *(float4*)&As[k][tr * 8 + 4];
            *(float4*)&br[0] = *(float4*)&Bs[k][tc * 4];
#pragma unroll
            for (int r = 0; r < 8; r++)
#pragma unroll
                for (int c = 0; c < 4; c++)
                    acc[r][c] += ar[r] * br[c];
        }
        __syncthreads();
    }
#pragma unroll
    for (int r = 0; r < 8; r++) {
        int row = row0 + tr * 8 + r;
        if (row < N_NODES) {
            float dv = g_dinv[row];
            float4 o = make_float4(acc[r][0] * dv, acc[r][1] * dv,
                                   acc[r][2] * dv, acc[r][3] * dv);
            g_hs2[row * 16 + tc] = o;
        }
    }
}

// ---------------- aggregation layer 2 + bias + log_softmax ----------------
// Warp per node; lanes 0..15 own float4 group lane; lanes 16..31 join shuffles.
__global__ void k_agg2(const float* __restrict__ b2, float* __restrict__ out) {
    int gw   = (blockIdx.x * blockDim.x + threadIdx.x) >> 5;
    int lane = threadIdx.x & 31;
    if (gw >= N_NODES) return;
    const float4* __restrict__ hs = g_hs2;
    const int* __restrict__ col = g_col;
    bool active = lane < 16;
    int li = active ? lane : 0;
    float4 acc = hs[gw * 16 + li];   // self loop
    float4 acc2 = make_float4(0.f, 0.f, 0.f, 0.f);
    int beg = g_rowptr[gw], end = g_rowptr[gw + 1];
    int e = beg;
    for (; e + 3 < end; e += 4) {
        int s0 = col[e];
        int s1 = col[e + 1];
        int s2 = col[e + 2];
        int s3 = col[e + 3];
        float4 v0 = hs[s0 * 16 + li];
        float4 v1 = hs[s1 * 16 + li];
        float4 v2 = hs[s2 * 16 + li];
        float4 v3 = hs[s3 * 16 + li];
        acc.x  += v0.x; acc.y  += v0.y; acc.z  += v0.z; acc.w  += v0.w;
        acc2.x += v1.x; acc2.y += v1.y; acc2.z += v1.z; acc2.w += v1.w;
        acc.x  += v2.x; acc.y  += v2.y; acc.z  += v2.z; acc.w  += v2.w;
        acc2.x += v3.x; acc2.y += v3.y; acc2.z += v3.z; acc2.w += v3.w;
    }
    for (; e < end; e++) {
        int s0 = col[e];
        float4 v0 = hs[s0 * 16 + li];
        acc.x += v0.x; acc.y += v0.y; acc.z += v0.z; acc.w += v0.w;
    }
    acc.x += acc2.x; acc.y += acc2.y; acc.z += acc2.z; acc.w += acc2.w;
    float dv = g_dinv[gw];
    float o0 = acc.x * dv + b2[li * 4 + 0];
    float o1 = acc.y * dv + b2[li * 4 + 1];
    float o2 = acc.z * dv + b2[li * 4 + 2];
    float o3 = acc.w * dv + b2[li * 4 + 3];
    // log_softmax over 64 values (4 per active lane)
    float m = fmaxf(fmaxf(o0, o1), fmaxf(o2, o3));
    if (!active) m = -1e30f;
#pragma unroll
    for (int off = 16; off; off >>= 1)
        m = fmaxf(m, __shfl_xor_sync(0xffffffffu, m, off));
    float s2 = active ? (expf(o0 - m) + expf(o1 - m) + expf(o2 - m) + expf(o3 - m)) : 0.f;
#pragma unroll
    for (int off = 16; off; off >>= 1)
        s2 += __shfl_xor_sync(0xffffffffu, s2, off);
    float lse = m + logf(s2);
    if (active) {
        out[gw * OUTD + lane * 4 + 0] = o0 - lse;
        out[gw * OUTD + lane * 4 + 1] = o1 - lse;
        out[gw * OUTD + lane * 4 + 2] = o2 - lse;
        out[gw * OUTD + lane * 4 + 3] = o3 - lse;
    }
}

// ---------------- launch ----------------
extern "C" void kernel_launch(void* const* d_in, const int* in_sizes, int n_in,
                              void* d_out, int out_size) {
    const float* x  = (const float*)d_in[0];
    const void*  ei = d_in[1];
    const float* W1 = (const float*)d_in[2];
    const float* b1 = (const float*)d_in[3];
    const float* W2 = (const float*)d_in[4];
    const float* b2 = (const float*)d_in[5];
    float* out = (float*)d_out;

    int E = in_sizes[1] / 2;
    if (E > E_MAX) E = E_MAX;

    int nblkN = (N_NODES + 255) / 256;
    int nblkE = (E + 255) / 256;
    int nblkM = (N_NODES + 127) / 128;          // GEMM row blocks
    int nblkW = (N_NODES * 32 + 255) / 256;     // warp-per-node kernels

    k_init<<<nblkN, 256>>>();
    k_detect<<<1, 1024>>>((const long long*)ei, E);
    k_edges<<<nblkE, 256>>>(ei, E);
    k_scan1<<<SCAN_NBLK, SCAN_BLK>>>();         // also computes dinv
    k_scan2<<<1, 128>>>();
    k_scan3<<<SCAN_NBLK, SCAN_BLK>>>(E);
    k_scatter<<<nblkE, 256>>>(E);
    k_gemm1<<<nblkM, 256>>>(x, W1);
    k_agg1<<<nblkW, 256>>>(b1);
    k_gemm2<<<nblkM, 256>>>(W2);
    k_agg2<<<nblkW, 256>>>(b2, out);
}